// round 6
// baseline (speedup 1.0000x reference)
#include <cuda_runtime.h>
#include <math.h>

#define Bq   2
#define Lq   4096
#define Dq   512
#define Hq   8
#define DKq  64
#define BHq  (Bq*Hq)
#define Mrows (Bq*Lq)          // 8192

// pair-permute within each 8-block: (t4, t4+4) become adjacent
__host__ __device__ __forceinline__ int PC(int c) {
    return (c & ~7) | ((c & 3) << 1) | ((c >> 2) & 1);
}

// ---------------- scratch (device globals; no allocations allowed) ----------
__device__ unsigned g_X [3 * Mrows * Dq];   // pc'd tf32 of q,k,v inputs
__device__ unsigned g_Wt[4 * Dq * Dq];      // [w][n][pc(k)] transposed weights
__device__ unsigned g_Q [BHq * Lq * DKq];   // [bh][l][pc(dk)], scaled 0.125*log2e
__device__ unsigned g_K [BHq * Lq * DKq];   // [bh][l][pc(dk)]
__device__ unsigned g_Vt[BHq * DKq * Lq];   // [bh][dk][pc(l)] (transposed)
__device__ unsigned g_ctx[Mrows * Dq];      // [b*L+l][pc(D)] tf32 bits

// ---------------- helpers -----------------------------------------------------
__device__ __forceinline__ unsigned f2tf(float f) {
    unsigned u;
    asm("cvt.rna.tf32.f32 %0, %1;" : "=r"(u) : "f"(f));
    return u;
}

__device__ __forceinline__ void mma8(float* c, const unsigned* a, const unsigned* b) {
    asm volatile(
        "mma.sync.aligned.m16n8k8.row.col.f32.tf32.tf32.f32 "
        "{%0,%1,%2,%3},{%4,%5,%6,%7},{%8,%9},{%0,%1,%2,%3};"
        : "+f"(c[0]), "+f"(c[1]), "+f"(c[2]), "+f"(c[3])
        : "r"(a[0]), "r"(a[1]), "r"(a[2]), "r"(a[3]),
          "r"(b[0]), "r"(b[1]));
}

__device__ __forceinline__ void cpa16(unsigned s, const void* g) {
    asm volatile("cp.async.cg.shared.global [%0], [%1], 16;" :: "r"(s), "l"(g));
}
#define CP_COMMIT asm volatile("cp.async.commit_group;")
#define CP_WAIT0  asm volatile("cp.async.wait_group 0;")

// ---------------- prep: x -> pc'd tf32 -----------------------------------------
__global__ __launch_bounds__(256) void prep_x(const float* __restrict__ q,
                                              const float* __restrict__ k,
                                              const float* __restrict__ v)
{
    const int which = blockIdx.y;
    const float* src = (which == 0) ? q : (which == 1) ? k : v;
    int idx = blockIdx.x * 256 + threadIdx.x;       // over Mrows*128 float4
    float4 t = ((const float4*)src)[idx];
    int c = (idx & 127) << 2;                       // col 0..508, mult of 4
    int m = idx >> 7;
    unsigned* dst = g_X + (size_t)which * Mrows * Dq + (size_t)m * Dq + (c & ~7);
    int off = (c & 4) ? 1 : 0;                      // pc of {0..3} / {4..7}
    dst[off + 0] = f2tf(t.x);
    dst[off + 2] = f2tf(t.y);
    dst[off + 4] = f2tf(t.z);
    dst[off + 6] = f2tf(t.w);
}

// ---------------- prep: W -> transposed pc'd tf32 ------------------------------
__global__ void prep_w(const float* __restrict__ W0, const float* __restrict__ W1,
                       const float* __restrict__ W2, const float* __restrict__ W3)
{
    __shared__ float tile[32][33];
    const int wsel = blockIdx.z;
    const float* W = (wsel == 0) ? W0 : (wsel == 1) ? W1 : (wsel == 2) ? W2 : W3;
    const int k0 = blockIdx.x * 32, n0 = blockIdx.y * 32;
    const int tx = threadIdx.x, ty = threadIdx.y;
    tile[ty][tx] = W[(size_t)(k0 + ty) * Dq + n0 + tx];
    __syncthreads();
    int kk = k0 + tx;
    g_Wt[(size_t)wsel * Dq * Dq + (size_t)(n0 + ty) * Dq + (kk & ~7) + PC(kk & 7)]
        = f2tf(tile[tx][ty]);
}

// ---------------- tf32 GEMM, pre-formatted operands ----------------------------
// block 128x128, 8 warps, warp tile 64x32, BK=32, reg-prefetch double buffer
__global__ __launch_bounds__(256) void gemm_fast(
    const float* __restrict__ B0, const float* __restrict__ B1,
    const float* __restrict__ B2, float* __restrict__ out_plain, int mode_base)
{
    __shared__ unsigned As[128][36];
    __shared__ unsigned Bs[128][36];

    const int z = blockIdx.z;
    const int mode = mode_base + z;
    const unsigned* A  = (mode == 3) ? g_ctx : g_X + (size_t)z * Mrows * Dq;
    const unsigned* Wt = g_Wt + (size_t)((mode == 3) ? 3 : z) * Dq * Dq;
    const float* bias  = (z == 0) ? B0 : (z == 1) ? B1 : B2;

    const int m0 = blockIdx.y * 128;
    const int n0 = blockIdx.x * 128;
    const int tid = threadIdx.x;
    const int w = tid >> 5, lane = tid & 31;
    const int g = lane >> 2, t4 = lane & 3;
    const int wm = (w & 1) * 64;
    const int wn = (w >> 1) * 32;

    const int frow = tid >> 3;
    const int fcol = (tid & 7) << 2;

    float acc[4][4][4];
    #pragma unroll
    for (int mt = 0; mt < 4; mt++)
        #pragma unroll
        for (int nt = 0; nt < 4; nt++)
            #pragma unroll
            for (int r = 0; r < 4; r++) acc[mt][nt][r] = 0.f;

    uint4 pa[4], pb[4];
#define LDAB(K0)                                                               \
    {                                                                          \
        _Pragma("unroll")                                                      \
        for (int l = 0; l < 4; l++) {                                         \
            int r = frow + 32 * l;                                            \
            pa[l] = *(const uint4*)&A [(size_t)(m0 + r) * Dq + (K0) + fcol];  \
            pb[l] = *(const uint4*)&Wt[(size_t)(n0 + r) * Dq + (K0) + fcol];  \
        }                                                                      \
    }

    LDAB(0);

    for (int k0 = 0; k0 < Dq; k0 += 32) {
        #pragma unroll
        for (int l = 0; l < 4; l++) {
            int r = frow + 32 * l;
            *(uint4*)&As[r][fcol] = pa[l];
            *(uint4*)&Bs[r][fcol] = pb[l];
        }
        __syncthreads();

        if (k0 + 32 < Dq) LDAB(k0 + 32);

        #pragma unroll
        for (int kk = 0; kk < 32; kk += 8) {
            unsigned a[4][4], b[4][2];
            #pragma unroll
            for (int mt = 0; mt < 4; mt++) {
                int mr = wm + mt * 16;
                uint2 lo = *(const uint2*)&As[mr + g][kk + 2 * t4];
                uint2 hi = *(const uint2*)&As[mr + g + 8][kk + 2 * t4];
                a[mt][0] = lo.x; a[mt][1] = hi.x; a[mt][2] = lo.y; a[mt][3] = hi.y;
            }
            #pragma unroll
            for (int nt = 0; nt < 4; nt++) {
                uint2 bb = *(const uint2*)&Bs[wn + nt * 8 + g][kk + 2 * t4];
                b[nt][0] = bb.x; b[nt][1] = bb.y;
            }
            #pragma unroll
            for (int mt = 0; mt < 4; mt++)
                #pragma unroll
                for (int nt = 0; nt < 4; nt++)
                    mma8(acc[mt][nt], a[mt], b[nt]);
        }
        __syncthreads();
    }
#undef LDAB

    // epilogue
    #pragma unroll
    for (int mt = 0; mt < 4; mt++) {
        #pragma unroll
        for (int nt = 0; nt < 4; nt++) {
            #pragma unroll
            for (int rr = 0; rr < 4; rr++) {
                int m = m0 + wm + mt * 16 + g + ((rr >> 1) ? 8 : 0);
                int n = n0 + wn + nt * 8 + (t4 << 1) + (rr & 1);
                float val = acc[mt][nt][rr] + bias[n];
                if (mode == 3) {
                    out_plain[(size_t)m * Dq + n] = val;
                } else {
                    int bb = m >> 12, l = m & 4095, h = n >> 6, dk = n & 63;
                    size_t bh = (size_t)(bb * Hq + h);
                    if (mode == 0)   // fold 1/sqrt(64) * log2(e) into Q
                        g_Q[(bh * Lq + l) * 64 + PC(dk)] = f2tf(val * 0.18033688f);
                    else if (mode == 1)
                        g_K[(bh * Lq + l) * 64 + PC(dk)] = f2tf(val);
                    else
                        g_Vt[(bh * 64 + dk) * Lq + (l & ~7) + PC(l & 7)] = f2tf(val);
                }
            }
        }
    }
}

// ---------------- attention helpers --------------------------------------------
// base-2 online softmax (Q pre-scaled by log2e/8)
__device__ __forceinline__ void softmax_update(
    float s[8][4], float acc[8][4], float& m0, float& m1, float& l0, float& l1,
    bool diag, int r0, int r1, int jbase, int t4)
{
    if (diag) {
        #pragma unroll
        for (int nt = 0; nt < 8; nt++) {
            int j = jbase + nt * 8 + (t4 << 1);
            if (j     > r0) s[nt][0] = -INFINITY;
            if (j + 1 > r0) s[nt][1] = -INFINITY;
            if (j     > r1) s[nt][2] = -INFINITY;
            if (j + 1 > r1) s[nt][3] = -INFINITY;
        }
    }
    float t0 = -INFINITY, t1 = -INFINITY;
    #pragma unroll
    for (int nt = 0; nt < 8; nt++) {
        t0 = fmaxf(t0, fmaxf(s[nt][0], s[nt][1]));
        t1 = fmaxf(t1, fmaxf(s[nt][2], s[nt][3]));
    }
    t0 = fmaxf(t0, __shfl_xor_sync(0xffffffffu, t0, 1));
    t0 = fmaxf(t0, __shfl_xor_sync(0xffffffffu, t0, 2));
    t1 = fmaxf(t1, __shfl_xor_sync(0xffffffffu, t1, 1));
    t1 = fmaxf(t1, __shfl_xor_sync(0xffffffffu, t1, 2));

    float mn0 = fmaxf(m0, t0), mn1 = fmaxf(m1, t1);
    float c0 = exp2f(m0 - mn0), c1 = exp2f(m1 - mn1);
    #pragma unroll
    for (int nt = 0; nt < 8; nt++) {
        acc[nt][0] *= c0; acc[nt][1] *= c0;
        acc[nt][2] *= c1; acc[nt][3] *= c1;
    }
    l0 *= c0; l1 *= c1;
    #pragma unroll
    for (int nt = 0; nt < 8; nt++) {
        float p0 = exp2f(s[nt][0] - mn0);
        float p1 = exp2f(s[nt][1] - mn0);
        float p2 = exp2f(s[nt][2] - mn1);
        float p3 = exp2f(s[nt][3] - mn1);
        s[nt][0] = p0; s[nt][1] = p1; s[nt][2] = p2; s[nt][3] = p3;
        l0 += p0 + p1; l1 += p2 + p3;
    }
    m0 = mn0; m1 = mn1;
}

__device__ __forceinline__ void make_pa(unsigned pa[4], const float s4[4],
                                        int src0, int e)
{
    float v00 = __shfl_sync(0xffffffffu, s4[0], src0);
    float v01 = __shfl_sync(0xffffffffu, s4[1], src0);
    float v20 = __shfl_sync(0xffffffffu, s4[0], src0 + 2);
    float v21 = __shfl_sync(0xffffffffu, s4[1], src0 + 2);
    float v10 = __shfl_sync(0xffffffffu, s4[2], src0);
    float v11 = __shfl_sync(0xffffffffu, s4[3], src0);
    float v30 = __shfl_sync(0xffffffffu, s4[2], src0 + 2);
    float v31 = __shfl_sync(0xffffffffu, s4[3], src0 + 2);
    pa[0] = f2tf(e ? v01 : v00);
    pa[1] = f2tf(e ? v11 : v10);
    pa[2] = f2tf(e ? v21 : v20);
    pa[3] = f2tf(e ? v31 : v30);
}

// ---------------- causal flash attention, double-buffered K/V -------------------
// 128 thr (4 warps); dynamic smem = 4 buffers of 64x72 words (72 KB);
// one cp.async wait + one __syncthreads per iteration.
#define TSTRIDE 72
#define TWORDS  (64 * TSTRIDE)

__global__ __launch_bounds__(128, 3) void attn_tf32(void)
{
    extern __shared__ unsigned sm[];
    unsigned* Kbuf[2] = { sm,              sm + TWORDS     };
    unsigned* Vbuf[2] = { sm + 2 * TWORDS, sm + 3 * TWORDS };

    const int qt = 63 - blockIdx.x;
    const int bh = blockIdx.y;
    const int tid = threadIdx.x;
    const int w = tid >> 5, lane = tid & 31;
    const int g = lane >> 2, t4 = lane & 3;
    const int src0 = (lane & ~3) | (t4 >> 1);
    const int e = t4 & 1;

    const unsigned* Qb = g_Q + (size_t)bh * Lq * 64;
    const unsigned* Kb = g_K + (size_t)bh * Lq * 64;
    const unsigned* Vb = g_Vt + (size_t)bh * 64 * Lq;

    const int r0 = qt * 64 + w * 16 + g, r1 = r0 + 8;

    // per-thread fill coords (8 chunks of 16B each over a 64x64 tile)
    const int frK = tid >> 4;                // advances by 8 per l
    const int fcK = (tid & 15) << 2;

    unsigned qa[8][4];
    #pragma unroll
    for (int kk = 0; kk < 8; kk++) {
        uint2 lo = *(const uint2*)&Qb[(size_t)r0 * 64 + kk * 8 + 2 * t4];
        uint2 hi = *(const uint2*)&Qb[(size_t)r1 * 64 + kk * 8 + 2 * t4];
        qa[kk][0] = lo.x; qa[kk][1] = hi.x; qa[kk][2] = lo.y; qa[kk][3] = hi.y;
    }

    float acc[8][4];
    #pragma unroll
    for (int nt = 0; nt < 8; nt++)
        #pragma unroll
        for (int r = 0; r < 4; r++) acc[nt][r] = 0.f;
    float m0 = -INFINITY, m1 = -INFINITY, l0 = 0.f, l1 = 0.f;

#define FILL_KV(KD, VD, KT)                                                    \
    {                                                                          \
        _Pragma("unroll")                                                      \
        for (int l = 0; l < 8; l++) {                                         \
            int r = frK + 8 * l;                                              \
            cpa16((unsigned)__cvta_generic_to_shared(&(KD)[r * TSTRIDE + fcK]),\
                  &Kb[((size_t)((KT) * 64 + r)) * 64 + fcK]);                 \
            cpa16((unsigned)__cvta_generic_to_shared(&(VD)[r * TSTRIDE + fcK]),\
                  &Vb[(size_t)r * Lq + (KT) * 64 + fcK]);                     \
        }                                                                      \
    }

    // prologue: fill buffers 0 with tile 0
    FILL_KV(Kbuf[0], Vbuf[0], 0);
    CP_COMMIT;
    CP_WAIT0;
    __syncthreads();

    for (int kt = 0; kt <= qt; kt++) {
        const int cur = kt & 1, nxt = cur ^ 1;
        const unsigned* Kc = Kbuf[cur];
        const unsigned* Vc = Vbuf[cur];

        // issue next-tile fills; they overlap the whole iteration body
        if (kt < qt) {
            FILL_KV(Kbuf[nxt], Vbuf[nxt], kt + 1);
            CP_COMMIT;
        }

        // ---- S = Q @ K^T ----
        float s[8][4];
        #pragma unroll
        for (int nt = 0; nt < 8; nt++)
            #pragma unroll
            for (int r = 0; r < 4; r++) s[nt][r] = 0.f;
        #pragma unroll
        for (int nt = 0; nt < 8; nt++) {
            #pragma unroll
            for (int kk = 0; kk < 8; kk++) {
                uint2 bb = *(const uint2*)&Kc[(nt * 8 + g) * TSTRIDE + kk * 8 + 2 * t4];
                unsigned b2[2] = {bb.x, bb.y};
                mma8(s[nt], qa[kk], b2);
            }
        }

        softmax_update(s, acc, m0, m1, l0, l1, kt == qt, r0, r1, kt * 64, t4);

        // ---- acc += P @ V ----
        #pragma unroll
        for (int kk = 0; kk < 8; kk++) {
            unsigned pa[4];
            make_pa(pa, s[kk], src0, e);
            #pragma unroll
            for (int nt = 0; nt < 8; nt++) {
                uint2 bb = *(const uint2*)&Vc[(nt * 8 + g) * TSTRIDE + kk * 8 + 2 * t4];
                unsigned b2[2] = {bb.x, bb.y};
                mma8(acc[nt], pa, b2);
            }
        }

        if (kt < qt) CP_WAIT0;
        __syncthreads();
    }
#undef FILL_KV

    // epilogue -> g_ctx as pc'd tf32
    l0 += __shfl_xor_sync(0xffffffffu, l0, 1);
    l0 += __shfl_xor_sync(0xffffffffu, l0, 2);
    l1 += __shfl_xor_sync(0xffffffffu, l1, 1);
    l1 += __shfl_xor_sync(0xffffffffu, l1, 2);
    const float i0 = 1.f / l0, i1 = 1.f / l1;

    const int b = bh >> 3, h = bh & 7;
    #pragma unroll
    for (int nt = 0; nt < 8; nt++) {
        int c0 = nt * 8 + (t4 << 1);
        int col0 = h * 64 + (c0 & ~7) + PC(c0 & 7);
        int col1 = h * 64 + ((c0 + 1) & ~7) + PC((c0 + 1) & 7);
        g_ctx[((size_t)(b * Lq) + r0) * Dq + col0] = f2tf(acc[nt][0] * i0);
        g_ctx[((size_t)(b * Lq) + r0) * Dq + col1] = f2tf(acc[nt][1] * i0);
        g_ctx[((size_t)(b * Lq) + r1) * Dq + col0] = f2tf(acc[nt][2] * i1);
        g_ctx[((size_t)(b * Lq) + r1) * Dq + col1] = f2tf(acc[nt][3] * i1);
    }
}

// ---------------- launch --------------------------------------------------------
extern "C" void kernel_launch(void* const* d_in, const int* in_sizes, int n_in,
                              void* d_out, int out_size)
{
    const float* q  = (const float*)d_in[0];
    const float* k  = (const float*)d_in[1];
    const float* v  = (const float*)d_in[2];
    // d_in[3] = mask (int32 tril) — causality handled analytically
    const float* Wq = (const float*)d_in[4];
    const float* bq = (const float*)d_in[5];
    const float* Wk = (const float*)d_in[6];
    const float* bk = (const float*)d_in[7];
    const float* Wv = (const float*)d_in[8];
    const float* bv = (const float*)d_in[9];
    const float* Wo = (const float*)d_in[10];
    const float* bo = (const float*)d_in[11];
    float* out = (float*)d_out;

    static int smem_set = 0;
    if (!smem_set) {
        cudaFuncSetAttribute(attn_tf32, cudaFuncAttributeMaxDynamicSharedMemorySize,
                             4 * TWORDS * 4);
        smem_set = 1;
    }

    prep_x<<<dim3(Mrows * 128 / 256, 3), 256>>>(q, k, v);
    prep_w<<<dim3(16, 16, 4), dim3(32, 32)>>>(Wq, Wk, Wv, Wo);

    gemm_fast<<<dim3(4, 64, 3), 256>>>(bq, bk, bv, nullptr, 0);

    attn_tf32<<<dim3(64, BHq), 128, 4 * TWORDS * 4>>>();

    gemm_fast<<<dim3(4, 64, 1), 256>>>(bo, nullptr, nullptr, out, 3);
}

// round 7
// speedup vs baseline: 1.0315x; 1.0315x over previous
#include <cuda_runtime.h>
#include <math.h>

#define Bq   2
#define Lq   4096
#define Dq   512
#define Hq   8
#define DKq  64
#define BHq  (Bq*Hq)
#define Mrows (Bq*Lq)          // 8192

// pair-permute within each 8-block: (t4, t4+4) become adjacent
__host__ __device__ __forceinline__ int PC(int c) {
    return (c & ~7) | ((c & 3) << 1) | ((c >> 2) & 1);
}

// ---------------- scratch (device globals; no allocations allowed) ----------
__device__ unsigned g_X [3 * Mrows * Dq];   // pc'd tf32 of q,k,v inputs
__device__ unsigned g_Wt[4 * Dq * Dq];      // [w][n][pc(k)] transposed weights
__device__ unsigned g_Q [BHq * Lq * DKq];   // [bh][l][pc(dk)], scaled 0.125*log2e
__device__ unsigned g_K [BHq * Lq * DKq];   // [bh][l][pc(dk)]
__device__ unsigned g_Vt[BHq * DKq * Lq];   // [bh][dk][pc(l)] (transposed)
__device__ unsigned g_ctx[Mrows * Dq];      // [b*L+l][pc(D)] tf32 bits

// ---------------- helpers -----------------------------------------------------
__device__ __forceinline__ unsigned f2tf(float f) {
    unsigned u;
    asm("cvt.rna.tf32.f32 %0, %1;" : "=r"(u) : "f"(f));
    return u;
}

__device__ __forceinline__ float ex2(float f) {
    float r;
    asm("ex2.approx.f32 %0, %1;" : "=f"(r) : "f"(f));
    return r;
}

__device__ __forceinline__ void mma8(float* c, const unsigned* a, const unsigned* b) {
    asm volatile(
        "mma.sync.aligned.m16n8k8.row.col.f32.tf32.tf32.f32 "
        "{%0,%1,%2,%3},{%4,%5,%6,%7},{%8,%9},{%0,%1,%2,%3};"
        : "+f"(c[0]), "+f"(c[1]), "+f"(c[2]), "+f"(c[3])
        : "r"(a[0]), "r"(a[1]), "r"(a[2]), "r"(a[3]),
          "r"(b[0]), "r"(b[1]));
}

__device__ __forceinline__ void cpa16(unsigned s, const void* g) {
    asm volatile("cp.async.cg.shared.global [%0], [%1], 16;" :: "r"(s), "l"(g));
}
#define CP_COMMIT asm volatile("cp.async.commit_group;")
#define CP_WAIT0  asm volatile("cp.async.wait_group 0;")

// ---------------- prep: x -> pc'd tf32 -----------------------------------------
__global__ __launch_bounds__(256) void prep_x(const float* __restrict__ q,
                                              const float* __restrict__ k,
                                              const float* __restrict__ v)
{
    const int which = blockIdx.y;
    const float* src = (which == 0) ? q : (which == 1) ? k : v;
    int idx = blockIdx.x * 256 + threadIdx.x;       // over Mrows*128 float4
    float4 t = ((const float4*)src)[idx];
    int c = (idx & 127) << 2;                       // col 0..508, mult of 4
    int m = idx >> 7;
    unsigned* dst = g_X + (size_t)which * Mrows * Dq + (size_t)m * Dq + (c & ~7);
    int off = (c & 4) ? 1 : 0;                      // pc of {0..3} / {4..7}
    dst[off + 0] = f2tf(t.x);
    dst[off + 2] = f2tf(t.y);
    dst[off + 4] = f2tf(t.z);
    dst[off + 6] = f2tf(t.w);
}

// ---------------- prep: W -> transposed pc'd tf32 ------------------------------
__global__ void prep_w(const float* __restrict__ W0, const float* __restrict__ W1,
                       const float* __restrict__ W2, const float* __restrict__ W3)
{
    __shared__ float tile[32][33];
    const int wsel = blockIdx.z;
    const float* W = (wsel == 0) ? W0 : (wsel == 1) ? W1 : (wsel == 2) ? W2 : W3;
    const int k0 = blockIdx.x * 32, n0 = blockIdx.y * 32;
    const int tx = threadIdx.x, ty = threadIdx.y;
    tile[ty][tx] = W[(size_t)(k0 + ty) * Dq + n0 + tx];
    __syncthreads();
    int kk = k0 + tx;
    g_Wt[(size_t)wsel * Dq * Dq + (size_t)(n0 + ty) * Dq + (kk & ~7) + PC(kk & 7)]
        = f2tf(tile[tx][ty]);
}

// ---------------- tf32 GEMM, pre-formatted operands ----------------------------
// block 128x128, 8 warps, warp tile 64x32, BK=32, reg-prefetch double buffer
__global__ __launch_bounds__(256) void gemm_fast(
    const float* __restrict__ B0, const float* __restrict__ B1,
    const float* __restrict__ B2, float* __restrict__ out_plain, int mode_base)
{
    __shared__ unsigned As[128][36];
    __shared__ unsigned Bs[128][36];

    const int z = blockIdx.z;
    const int mode = mode_base + z;
    const unsigned* A  = (mode == 3) ? g_ctx : g_X + (size_t)z * Mrows * Dq;
    const unsigned* Wt = g_Wt + (size_t)((mode == 3) ? 3 : z) * Dq * Dq;
    const float* bias  = (z == 0) ? B0 : (z == 1) ? B1 : B2;

    const int m0 = blockIdx.y * 128;
    const int n0 = blockIdx.x * 128;
    const int tid = threadIdx.x;
    const int w = tid >> 5, lane = tid & 31;
    const int g = lane >> 2, t4 = lane & 3;
    const int wm = (w & 1) * 64;
    const int wn = (w >> 1) * 32;

    const int frow = tid >> 3;
    const int fcol = (tid & 7) << 2;

    float acc[4][4][4];
    #pragma unroll
    for (int mt = 0; mt < 4; mt++)
        #pragma unroll
        for (int nt = 0; nt < 4; nt++)
            #pragma unroll
            for (int r = 0; r < 4; r++) acc[mt][nt][r] = 0.f;

    uint4 pa[4], pb[4];
#define LDAB(K0)                                                               \
    {                                                                          \
        _Pragma("unroll")                                                      \
        for (int l = 0; l < 4; l++) {                                         \
            int r = frow + 32 * l;                                            \
            pa[l] = *(const uint4*)&A [(size_t)(m0 + r) * Dq + (K0) + fcol];  \
            pb[l] = *(const uint4*)&Wt[(size_t)(n0 + r) * Dq + (K0) + fcol];  \
        }                                                                      \
    }

    LDAB(0);

    for (int k0 = 0; k0 < Dq; k0 += 32) {
        #pragma unroll
        for (int l = 0; l < 4; l++) {
            int r = frow + 32 * l;
            *(uint4*)&As[r][fcol] = pa[l];
            *(uint4*)&Bs[r][fcol] = pb[l];
        }
        __syncthreads();

        if (k0 + 32 < Dq) LDAB(k0 + 32);

        #pragma unroll
        for (int kk = 0; kk < 32; kk += 8) {
            unsigned a[4][4], b[4][2];
            #pragma unroll
            for (int mt = 0; mt < 4; mt++) {
                int mr = wm + mt * 16;
                uint2 lo = *(const uint2*)&As[mr + g][kk + 2 * t4];
                uint2 hi = *(const uint2*)&As[mr + g + 8][kk + 2 * t4];
                a[mt][0] = lo.x; a[mt][1] = hi.x; a[mt][2] = lo.y; a[mt][3] = hi.y;
            }
            #pragma unroll
            for (int nt = 0; nt < 4; nt++) {
                uint2 bb = *(const uint2*)&Bs[wn + nt * 8 + g][kk + 2 * t4];
                b[nt][0] = bb.x; b[nt][1] = bb.y;
            }
            #pragma unroll
            for (int mt = 0; mt < 4; mt++)
                #pragma unroll
                for (int nt = 0; nt < 4; nt++)
                    mma8(acc[mt][nt], a[mt], b[nt]);
        }
        __syncthreads();
    }
#undef LDAB

    // epilogue
    #pragma unroll
    for (int mt = 0; mt < 4; mt++) {
        #pragma unroll
        for (int nt = 0; nt < 4; nt++) {
            #pragma unroll
            for (int rr = 0; rr < 4; rr++) {
                int m = m0 + wm + mt * 16 + g + ((rr >> 1) ? 8 : 0);
                int n = n0 + wn + nt * 8 + (t4 << 1) + (rr & 1);
                float val = acc[mt][nt][rr] + bias[n];
                if (mode == 3) {
                    out_plain[(size_t)m * Dq + n] = val;
                } else {
                    int bb = m >> 12, l = m & 4095, h = n >> 6, dk = n & 63;
                    size_t bh = (size_t)(bb * Hq + h);
                    if (mode == 0)   // fold 1/sqrt(64) * log2(e) into Q
                        g_Q[(bh * Lq + l) * 64 + PC(dk)] = f2tf(val * 0.18033688f);
                    else if (mode == 1)
                        g_K[(bh * Lq + l) * 64 + PC(dk)] = f2tf(val);
                    else
                        g_Vt[(bh * 64 + dk) * Lq + (l & ~7) + PC(l & 7)] = f2tf(val);
                }
            }
        }
    }
}

// ---------------- attention helpers --------------------------------------------
// base-2 online softmax (Q pre-scaled by log2e/8)
__device__ __forceinline__ void softmax_update(
    float s[8][4], float acc[8][4], float& m0, float& m1, float& l0, float& l1,
    bool diag, int r0, int r1, int jbase, int t4)
{
    if (diag) {
        #pragma unroll
        for (int nt = 0; nt < 8; nt++) {
            int j = jbase + nt * 8 + (t4 << 1);
            if (j     > r0) s[nt][0] = -INFINITY;
            if (j + 1 > r0) s[nt][1] = -INFINITY;
            if (j     > r1) s[nt][2] = -INFINITY;
            if (j + 1 > r1) s[nt][3] = -INFINITY;
        }
    }
    float t0 = -INFINITY, t1 = -INFINITY;
    #pragma unroll
    for (int nt = 0; nt < 8; nt++) {
        t0 = fmaxf(t0, fmaxf(s[nt][0], s[nt][1]));
        t1 = fmaxf(t1, fmaxf(s[nt][2], s[nt][3]));
    }
    t0 = fmaxf(t0, __shfl_xor_sync(0xffffffffu, t0, 1));
    t0 = fmaxf(t0, __shfl_xor_sync(0xffffffffu, t0, 2));
    t1 = fmaxf(t1, __shfl_xor_sync(0xffffffffu, t1, 1));
    t1 = fmaxf(t1, __shfl_xor_sync(0xffffffffu, t1, 2));

    float mn0 = fmaxf(m0, t0), mn1 = fmaxf(m1, t1);
    float c0 = ex2(m0 - mn0), c1 = ex2(m1 - mn1);
    #pragma unroll
    for (int nt = 0; nt < 8; nt++) {
        acc[nt][0] *= c0; acc[nt][1] *= c0;
        acc[nt][2] *= c1; acc[nt][3] *= c1;
    }
    l0 *= c0; l1 *= c1;
    #pragma unroll
    for (int nt = 0; nt < 8; nt++) {
        float p0 = ex2(s[nt][0] - mn0);
        float p1 = ex2(s[nt][1] - mn0);
        float p2 = ex2(s[nt][2] - mn1);
        float p3 = ex2(s[nt][3] - mn1);
        s[nt][0] = p0; s[nt][1] = p1; s[nt][2] = p2; s[nt][3] = p3;
        l0 += p0 + p1; l1 += p2 + p3;
    }
    m0 = mn0; m1 = mn1;
}

__device__ __forceinline__ void make_pa(unsigned pa[4], const float s4[4],
                                        int src0, int e)
{
    float v00 = __shfl_sync(0xffffffffu, s4[0], src0);
    float v01 = __shfl_sync(0xffffffffu, s4[1], src0);
    float v20 = __shfl_sync(0xffffffffu, s4[0], src0 + 2);
    float v21 = __shfl_sync(0xffffffffu, s4[1], src0 + 2);
    float v10 = __shfl_sync(0xffffffffu, s4[2], src0);
    float v11 = __shfl_sync(0xffffffffu, s4[3], src0);
    float v30 = __shfl_sync(0xffffffffu, s4[2], src0 + 2);
    float v31 = __shfl_sync(0xffffffffu, s4[3], src0 + 2);
    pa[0] = f2tf(e ? v01 : v00);
    pa[1] = f2tf(e ? v11 : v10);
    pa[2] = f2tf(e ? v21 : v20);
    pa[3] = f2tf(e ? v31 : v30);
}

// ---------------- causal flash attention (R5 structure, 4 blocks/SM) ------------
__global__ __launch_bounds__(128, 4) void attn_tf32(void)
{
    __shared__ unsigned Ks[64][72];
    __shared__ unsigned VT[64][72];

    const int qt = 63 - blockIdx.x;
    const int bh = blockIdx.y;
    const int tid = threadIdx.x;
    const int w = tid >> 5, lane = tid & 31;
    const int g = lane >> 2, t4 = lane & 3;
    const int src0 = (lane & ~3) | (t4 >> 1);
    const int e = t4 & 1;

    const unsigned* Qb = g_Q + (size_t)bh * Lq * 64;
    const unsigned* Kb = g_K + (size_t)bh * Lq * 64;
    const unsigned* Vb = g_Vt + (size_t)bh * 64 * Lq;

    const int r0 = qt * 64 + w * 16 + g, r1 = r0 + 8;

    unsigned qa[8][4];
    #pragma unroll
    for (int kk = 0; kk < 8; kk++) {
        uint2 lo = *(const uint2*)&Qb[(size_t)r0 * 64 + kk * 8 + 2 * t4];
        uint2 hi = *(const uint2*)&Qb[(size_t)r1 * 64 + kk * 8 + 2 * t4];
        qa[kk][0] = lo.x; qa[kk][1] = hi.x; qa[kk][2] = lo.y; qa[kk][3] = hi.y;
    }

    float acc[8][4];
    #pragma unroll
    for (int nt = 0; nt < 8; nt++)
        #pragma unroll
        for (int r = 0; r < 4; r++) acc[nt][r] = 0.f;
    float m0 = -INFINITY, m1 = -INFINITY, l0 = 0.f, l1 = 0.f;

    #pragma unroll
    for (int l = 0; l < 8; l++) {
        int ee = tid + l * 128;
        int r = ee >> 4, c4 = (ee & 15) << 2;
        cpa16((unsigned)__cvta_generic_to_shared(&Ks[r][c4]),
              &Kb[((size_t)r) * 64 + c4]);
    }
    CP_COMMIT;
    CP_WAIT0;
    __syncthreads();

    for (int kt = 0; kt <= qt; kt++) {
        // issue V(kt) fill (overlaps QK + softmax)
        #pragma unroll
        for (int l = 0; l < 8; l++) {
            int ee = tid + l * 128;
            int r = ee >> 4, c4 = (ee & 15) << 2;
            cpa16((unsigned)__cvta_generic_to_shared(&VT[r][c4]),
                  &Vb[(size_t)r * Lq + kt * 64 + c4]);
        }
        CP_COMMIT;

        // ---- S = Q @ K^T ----
        float s[8][4];
        #pragma unroll
        for (int nt = 0; nt < 8; nt++)
            #pragma unroll
            for (int r = 0; r < 4; r++) s[nt][r] = 0.f;
        #pragma unroll
        for (int nt = 0; nt < 8; nt++) {
            #pragma unroll
            for (int kk = 0; kk < 8; kk++) {
                uint2 bb = *(const uint2*)&Ks[nt * 8 + g][kk * 8 + 2 * t4];
                unsigned b2[2] = {bb.x, bb.y};
                mma8(s[nt], qa[kk], b2);
            }
        }

        softmax_update(s, acc, m0, m1, l0, l1, kt == qt, r0, r1, kt * 64, t4);

        CP_WAIT0;
        __syncthreads();    // VT ready; all warps done reading Ks

        // issue K(kt+1) fill (overlaps PV)
        if (kt < qt) {
            #pragma unroll
            for (int l = 0; l < 8; l++) {
                int ee = tid + l * 128;
                int r = ee >> 4, c4 = (ee & 15) << 2;
                cpa16((unsigned)__cvta_generic_to_shared(&Ks[r][c4]),
                      &Kb[((size_t)((kt + 1) * 64 + r)) * 64 + c4]);
            }
            CP_COMMIT;
        }

        // ---- acc += P @ V ----
        #pragma unroll
        for (int kk = 0; kk < 8; kk++) {
            unsigned pa[4];
            make_pa(pa, s[kk], src0, e);
            #pragma unroll
            for (int nt = 0; nt < 8; nt++) {
                uint2 bb = *(const uint2*)&VT[nt * 8 + g][kk * 8 + 2 * t4];
                unsigned b2[2] = {bb.x, bb.y};
                mma8(acc[nt], pa, b2);
            }
        }

        CP_WAIT0;
        __syncthreads();    // Ks(kt+1) ready; all warps done reading VT
    }

    // epilogue -> g_ctx as pc'd tf32
    l0 += __shfl_xor_sync(0xffffffffu, l0, 1);
    l0 += __shfl_xor_sync(0xffffffffu, l0, 2);
    l1 += __shfl_xor_sync(0xffffffffu, l1, 1);
    l1 += __shfl_xor_sync(0xffffffffu, l1, 2);
    const float i0 = 1.f / l0, i1 = 1.f / l1;

    const int b = bh >> 3, h = bh & 7;
    #pragma unroll
    for (int nt = 0; nt < 8; nt++) {
        int c0 = nt * 8 + (t4 << 1);
        int col0 = h * 64 + (c0 & ~7) + PC(c0 & 7);
        int col1 = h * 64 + ((c0 + 1) & ~7) + PC((c0 + 1) & 7);
        g_ctx[((size_t)(b * Lq) + r0) * Dq + col0] = f2tf(acc[nt][0] * i0);
        g_ctx[((size_t)(b * Lq) + r0) * Dq + col1] = f2tf(acc[nt][1] * i0);
        g_ctx[((size_t)(b * Lq) + r1) * Dq + col0] = f2tf(acc[nt][2] * i1);
        g_ctx[((size_t)(b * Lq) + r1) * Dq + col1] = f2tf(acc[nt][3] * i1);
    }
}

// ---------------- launch --------------------------------------------------------
extern "C" void kernel_launch(void* const* d_in, const int* in_sizes, int n_in,
                              void* d_out, int out_size)
{
    const float* q  = (const float*)d_in[0];
    const float* k  = (const float*)d_in[1];
    const float* v  = (const float*)d_in[2];
    // d_in[3] = mask (int32 tril) — causality handled analytically
    const float* Wq = (const float*)d_in[4];
    const float* bq = (const float*)d_in[5];
    const float* Wk = (const float*)d_in[6];
    const float* bk = (const float*)d_in[7];
    const float* Wv = (const float*)d_in[8];
    const float* bv = (const float*)d_in[9];
    const float* Wo = (const float*)d_in[10];
    const float* bo = (const float*)d_in[11];
    float* out = (float*)d_out;

    prep_x<<<dim3(Mrows * 128 / 256, 3), 256>>>(q, k, v);
    prep_w<<<dim3(16, 16, 4), dim3(32, 32)>>>(Wq, Wk, Wv, Wo);

    gemm_fast<<<dim3(4, 64, 3), 256>>>(bq, bk, bv, nullptr, 0);

    attn_tf32<<<dim3(64, BHq), 128>>>();

    gemm_fast<<<dim3(4, 64, 1), 256>>>(bo, nullptr, nullptr, out, 3);
}

// round 8
// speedup vs baseline: 1.1409x; 1.1060x over previous
#include <cuda_runtime.h>
#include <math.h>

#define Bq   2
#define Lq   4096
#define Dq   512
#define Hq   8
#define DKq  64
#define BHq  (Bq*Hq)
#define Mrows (Bq*Lq)          // 8192

// pair-permute within each 8-block: (t4, t4+4) become adjacent
__host__ __device__ __forceinline__ int PC(int c) {
    return (c & ~7) | ((c & 3) << 1) | ((c >> 2) & 1);
}

// ---------------- scratch (device globals; no allocations allowed) ----------
__device__ unsigned g_X [3 * Mrows * Dq];   // pc'd tf32 of q,k,v inputs
__device__ unsigned g_Wt[4 * Dq * Dq];      // [w][n][pc(k)] transposed weights
__device__ unsigned g_Q [BHq * Lq * DKq];   // [bh][l][pc(dk)], scaled 0.125*log2e
__device__ unsigned g_K [BHq * Lq * DKq];   // [bh][l][pc(dk)]
__device__ unsigned g_Vt[BHq * DKq * Lq];   // [bh][dk][pc(l)] (transposed)
__device__ unsigned g_ctx[Mrows * Dq];      // [b*L+l][pc(D)] tf32 bits

// ---------------- helpers -----------------------------------------------------
__device__ __forceinline__ unsigned f2tf(float f) {
    unsigned u;
    asm("cvt.rna.tf32.f32 %0, %1;" : "=r"(u) : "f"(f));
    return u;
}

__device__ __forceinline__ float ex2(float f) {
    float r;
    asm("ex2.approx.f32 %0, %1;" : "=f"(r) : "f"(f));
    return r;
}

__device__ __forceinline__ void mma8(float* c, const unsigned* a, const unsigned* b) {
    asm volatile(
        "mma.sync.aligned.m16n8k8.row.col.f32.tf32.tf32.f32 "
        "{%0,%1,%2,%3},{%4,%5,%6,%7},{%8,%9},{%0,%1,%2,%3};"
        : "+f"(c[0]), "+f"(c[1]), "+f"(c[2]), "+f"(c[3])
        : "r"(a[0]), "r"(a[1]), "r"(a[2]), "r"(a[3]),
          "r"(b[0]), "r"(b[1]));
}

__device__ __forceinline__ void cpa16(unsigned s, const void* g) {
    asm volatile("cp.async.cg.shared.global [%0], [%1], 16;" :: "r"(s), "l"(g));
}
#define CP_COMMIT asm volatile("cp.async.commit_group;")
#define CP_WAIT0  asm volatile("cp.async.wait_group 0;")
#define CP_WAIT1  asm volatile("cp.async.wait_group 1;")

// ---------------- prep: x -> pc'd tf32 -----------------------------------------
__global__ __launch_bounds__(256) void prep_x(const float* __restrict__ q,
                                              const float* __restrict__ k,
                                              const float* __restrict__ v)
{
    const int which = blockIdx.y;
    const float* src = (which == 0) ? q : (which == 1) ? k : v;
    int idx = blockIdx.x * 256 + threadIdx.x;       // over Mrows*128 float4
    float4 t = ((const float4*)src)[idx];
    int c = (idx & 127) << 2;                       // col 0..508, mult of 4
    int m = idx >> 7;
    unsigned* dst = g_X + (size_t)which * Mrows * Dq + (size_t)m * Dq + (c & ~7);
    int off = (c & 4) ? 1 : 0;                      // pc of {0..3} / {4..7}
    dst[off + 0] = f2tf(t.x);
    dst[off + 2] = f2tf(t.y);
    dst[off + 4] = f2tf(t.z);
    dst[off + 6] = f2tf(t.w);
}

// ---------------- prep: W -> transposed pc'd tf32 ------------------------------
__global__ void prep_w(const float* __restrict__ W0, const float* __restrict__ W1,
                       const float* __restrict__ W2, const float* __restrict__ W3)
{
    __shared__ float tile[32][33];
    const int wsel = blockIdx.z;
    const float* W = (wsel == 0) ? W0 : (wsel == 1) ? W1 : (wsel == 2) ? W2 : W3;
    const int k0 = blockIdx.x * 32, n0 = blockIdx.y * 32;
    const int tx = threadIdx.x, ty = threadIdx.y;
    tile[ty][tx] = W[(size_t)(k0 + ty) * Dq + n0 + tx];
    __syncthreads();
    int kk = k0 + tx;
    g_Wt[(size_t)wsel * Dq * Dq + (size_t)(n0 + ty) * Dq + (kk & ~7) + PC(kk & 7)]
        = f2tf(tile[tx][ty]);
}

// ---------------- tf32 GEMM, 3-stage cp.async pipeline --------------------------
// block 128x128, 8 warps, warp tile 64x32, BK=32
// dynamic smem: 3 stages x (A 128x36 + B 128x36) words = 110592 B
#define GST 4608                     // words per tile per stage (128*36)

__global__ __launch_bounds__(256, 2) void gemm_fast(
    const float* __restrict__ B0, const float* __restrict__ B1,
    const float* __restrict__ B2, float* __restrict__ out_plain, int mode_base)
{
    extern __shared__ unsigned sm[];

    const int z = blockIdx.z;
    const int mode = mode_base + z;
    const unsigned* A  = (mode == 3) ? g_ctx : g_X + (size_t)z * Mrows * Dq;
    const unsigned* Wt = g_Wt + (size_t)((mode == 3) ? 3 : z) * Dq * Dq;
    const float* bias  = (z == 0) ? B0 : (z == 1) ? B1 : B2;

    const int m0 = blockIdx.y * 128;
    const int n0 = blockIdx.x * 128;
    const int tid = threadIdx.x;
    const int w = tid >> 5, lane = tid & 31;
    const int g = lane >> 2, t4 = lane & 3;
    const int wm = (w & 1) * 64;
    const int wn = (w >> 1) * 32;

    float acc[4][4][4];
    #pragma unroll
    for (int mt = 0; mt < 4; mt++)
        #pragma unroll
        for (int nt = 0; nt < 4; nt++)
            #pragma unroll
            for (int r = 0; r < 4; r++) acc[mt][nt][r] = 0.f;

#define FILLG(ST, K0)                                                          \
    {                                                                          \
        unsigned* Ad = sm + (ST) * GST;                                        \
        unsigned* Bd = sm + 3 * GST + (ST) * GST;                              \
        _Pragma("unroll")                                                      \
        for (int l = 0; l < 4; l++) {                                         \
            int e = tid + l * 256;                                            \
            int r = e >> 3, c4 = (e & 7) << 2;                                \
            cpa16((unsigned)__cvta_generic_to_shared(&Ad[r * 36 + c4]),       \
                  &A [(size_t)(m0 + r) * Dq + (K0) + c4]);                    \
            cpa16((unsigned)__cvta_generic_to_shared(&Bd[r * 36 + c4]),       \
                  &Wt[(size_t)(n0 + r) * Dq + (K0) + c4]);                    \
        }                                                                      \
        CP_COMMIT;                                                             \
    }

    const int kIters = Dq / 32;        // 16
    FILLG(0, 0);
    FILLG(1, 32);

    for (int kt = 0; kt < kIters; kt++) {
        if (kt < kIters - 1) { CP_WAIT1; } else { CP_WAIT0; }
        __syncthreads();

        if (kt + 2 < kIters) FILLG((kt + 2) % 3, (kt + 2) * 32);

        const unsigned* As = sm + (kt % 3) * GST;
        const unsigned* Bs = sm + 3 * GST + (kt % 3) * GST;

        #pragma unroll
        for (int kk = 0; kk < 32; kk += 8) {
            unsigned a[4][4], b[4][2];
            #pragma unroll
            for (int mt = 0; mt < 4; mt++) {
                int mr = wm + mt * 16;
                uint2 lo = *(const uint2*)&As[(mr + g) * 36 + kk + 2 * t4];
                uint2 hi = *(const uint2*)&As[(mr + g + 8) * 36 + kk + 2 * t4];
                a[mt][0] = lo.x; a[mt][1] = hi.x; a[mt][2] = lo.y; a[mt][3] = hi.y;
            }
            #pragma unroll
            for (int nt = 0; nt < 4; nt++) {
                uint2 bb = *(const uint2*)&Bs[(wn + nt * 8 + g) * 36 + kk + 2 * t4];
                b[nt][0] = bb.x; b[nt][1] = bb.y;
            }
            #pragma unroll
            for (int mt = 0; mt < 4; mt++)
                #pragma unroll
                for (int nt = 0; nt < 4; nt++)
                    mma8(acc[mt][nt], a[mt], b[nt]);
        }
    }
#undef FILLG

    // epilogue
    #pragma unroll
    for (int mt = 0; mt < 4; mt++) {
        #pragma unroll
        for (int nt = 0; nt < 4; nt++) {
            #pragma unroll
            for (int rr = 0; rr < 4; rr++) {
                int m = m0 + wm + mt * 16 + g + ((rr >> 1) ? 8 : 0);
                int n = n0 + wn + nt * 8 + (t4 << 1) + (rr & 1);
                float val = acc[mt][nt][rr] + bias[n];
                if (mode == 3) {
                    out_plain[(size_t)m * Dq + n] = val;
                } else {
                    int bb = m >> 12, l = m & 4095, h = n >> 6, dk = n & 63;
                    size_t bh = (size_t)(bb * Hq + h);
                    if (mode == 0)   // fold 1/sqrt(64) * log2(e) into Q
                        g_Q[(bh * Lq + l) * 64 + PC(dk)] = f2tf(val * 0.18033688f);
                    else if (mode == 1)
                        g_K[(bh * Lq + l) * 64 + PC(dk)] = f2tf(val);
                    else
                        g_Vt[(bh * 64 + dk) * Lq + (l & ~7) + PC(l & 7)] = f2tf(val);
                }
            }
        }
    }
}

// ---------------- attention helpers --------------------------------------------
// base-2 online softmax (Q pre-scaled by log2e/8)
__device__ __forceinline__ void softmax_update(
    float s[8][4], float acc[8][4], float& m0, float& m1, float& l0, float& l1,
    bool diag, int r0, int r1, int jbase, int t4)
{
    if (diag) {
        #pragma unroll
        for (int nt = 0; nt < 8; nt++) {
            int j = jbase + nt * 8 + (t4 << 1);
            if (j     > r0) s[nt][0] = -INFINITY;
            if (j + 1 > r0) s[nt][1] = -INFINITY;
            if (j     > r1) s[nt][2] = -INFINITY;
            if (j + 1 > r1) s[nt][3] = -INFINITY;
        }
    }
    float t0 = -INFINITY, t1 = -INFINITY;
    #pragma unroll
    for (int nt = 0; nt < 8; nt++) {
        t0 = fmaxf(t0, fmaxf(s[nt][0], s[nt][1]));
        t1 = fmaxf(t1, fmaxf(s[nt][2], s[nt][3]));
    }
    t0 = fmaxf(t0, __shfl_xor_sync(0xffffffffu, t0, 1));
    t0 = fmaxf(t0, __shfl_xor_sync(0xffffffffu, t0, 2));
    t1 = fmaxf(t1, __shfl_xor_sync(0xffffffffu, t1, 1));
    t1 = fmaxf(t1, __shfl_xor_sync(0xffffffffu, t1, 2));

    float mn0 = fmaxf(m0, t0), mn1 = fmaxf(m1, t1);
    float c0 = ex2(m0 - mn0), c1 = ex2(m1 - mn1);
    #pragma unroll
    for (int nt = 0; nt < 8; nt++) {
        acc[nt][0] *= c0; acc[nt][1] *= c0;
        acc[nt][2] *= c1; acc[nt][3] *= c1;
    }
    l0 *= c0; l1 *= c1;
    #pragma unroll
    for (int nt = 0; nt < 8; nt++) {
        float p0 = ex2(s[nt][0] - mn0);
        float p1 = ex2(s[nt][1] - mn0);
        float p2 = ex2(s[nt][2] - mn1);
        float p3 = ex2(s[nt][3] - mn1);
        s[nt][0] = p0; s[nt][1] = p1; s[nt][2] = p2; s[nt][3] = p3;
        l0 += p0 + p1; l1 += p2 + p3;
    }
    m0 = mn0; m1 = mn1;
}

__device__ __forceinline__ void make_pa(unsigned pa[4], const float s4[4],
                                        int src0, int e)
{
    float v00 = __shfl_sync(0xffffffffu, s4[0], src0);
    float v01 = __shfl_sync(0xffffffffu, s4[1], src0);
    float v20 = __shfl_sync(0xffffffffu, s4[0], src0 + 2);
    float v21 = __shfl_sync(0xffffffffu, s4[1], src0 + 2);
    float v10 = __shfl_sync(0xffffffffu, s4[2], src0);
    float v11 = __shfl_sync(0xffffffffu, s4[3], src0);
    float v30 = __shfl_sync(0xffffffffu, s4[2], src0 + 2);
    float v31 = __shfl_sync(0xffffffffu, s4[3], src0 + 2);
    pa[0] = f2tf(e ? v01 : v00);
    pa[1] = f2tf(e ? v11 : v10);
    pa[2] = f2tf(e ? v21 : v20);
    pa[3] = f2tf(e ? v31 : v30);
}

// ---------------- causal flash attention (R7 structure, unchanged) --------------
__global__ __launch_bounds__(128, 4) void attn_tf32(void)
{
    __shared__ unsigned Ks[64][72];
    __shared__ unsigned VT[64][72];

    const int qt = 63 - blockIdx.x;
    const int bh = blockIdx.y;
    const int tid = threadIdx.x;
    const int w = tid >> 5, lane = tid & 31;
    const int g = lane >> 2, t4 = lane & 3;
    const int src0 = (lane & ~3) | (t4 >> 1);
    const int e = t4 & 1;

    const unsigned* Qb = g_Q + (size_t)bh * Lq * 64;
    const unsigned* Kb = g_K + (size_t)bh * Lq * 64;
    const unsigned* Vb = g_Vt + (size_t)bh * 64 * Lq;

    const int r0 = qt * 64 + w * 16 + g, r1 = r0 + 8;

    unsigned qa[8][4];
    #pragma unroll
    for (int kk = 0; kk < 8; kk++) {
        uint2 lo = *(const uint2*)&Qb[(size_t)r0 * 64 + kk * 8 + 2 * t4];
        uint2 hi = *(const uint2*)&Qb[(size_t)r1 * 64 + kk * 8 + 2 * t4];
        qa[kk][0] = lo.x; qa[kk][1] = hi.x; qa[kk][2] = lo.y; qa[kk][3] = hi.y;
    }

    float acc[8][4];
    #pragma unroll
    for (int nt = 0; nt < 8; nt++)
        #pragma unroll
        for (int r = 0; r < 4; r++) acc[nt][r] = 0.f;
    float m0 = -INFINITY, m1 = -INFINITY, l0 = 0.f, l1 = 0.f;

    #pragma unroll
    for (int l = 0; l < 8; l++) {
        int ee = tid + l * 128;
        int r = ee >> 4, c4 = (ee & 15) << 2;
        cpa16((unsigned)__cvta_generic_to_shared(&Ks[r][c4]),
              &Kb[((size_t)r) * 64 + c4]);
    }
    CP_COMMIT;
    CP_WAIT0;
    __syncthreads();

    for (int kt = 0; kt <= qt; kt++) {
        // issue V(kt) fill (overlaps QK + softmax)
        #pragma unroll
        for (int l = 0; l < 8; l++) {
            int ee = tid + l * 128;
            int r = ee >> 4, c4 = (ee & 15) << 2;
            cpa16((unsigned)__cvta_generic_to_shared(&VT[r][c4]),
                  &Vb[(size_t)r * Lq + kt * 64 + c4]);
        }
        CP_COMMIT;

        // ---- S = Q @ K^T ----
        float s[8][4];
        #pragma unroll
        for (int nt = 0; nt < 8; nt++)
            #pragma unroll
            for (int r = 0; r < 4; r++) s[nt][r] = 0.f;
        #pragma unroll
        for (int nt = 0; nt < 8; nt++) {
            #pragma unroll
            for (int kk = 0; kk < 8; kk++) {
                uint2 bb = *(const uint2*)&Ks[nt * 8 + g][kk * 8 + 2 * t4];
                unsigned b2[2] = {bb.x, bb.y};
                mma8(s[nt], qa[kk], b2);
            }
        }

        softmax_update(s, acc, m0, m1, l0, l1, kt == qt, r0, r1, kt * 64, t4);

        CP_WAIT0;
        __syncthreads();    // VT ready; all warps done reading Ks

        // issue K(kt+1) fill (overlaps PV)
        if (kt < qt) {
            #pragma unroll
            for (int l = 0; l < 8; l++) {
                int ee = tid + l * 128;
                int r = ee >> 4, c4 = (ee & 15) << 2;
                cpa16((unsigned)__cvta_generic_to_shared(&Ks[r][c4]),
                      &Kb[((size_t)((kt + 1) * 64 + r)) * 64 + c4]);
            }
            CP_COMMIT;
        }

        // ---- acc += P @ V ----
        #pragma unroll
        for (int kk = 0; kk < 8; kk++) {
            unsigned pa[4];
            make_pa(pa, s[kk], src0, e);
            #pragma unroll
            for (int nt = 0; nt < 8; nt++) {
                uint2 bb = *(const uint2*)&VT[nt * 8 + g][kk * 8 + 2 * t4];
                unsigned b2[2] = {bb.x, bb.y};
                mma8(acc[nt], pa, b2);
            }
        }

        CP_WAIT0;
        __syncthreads();    // Ks(kt+1) ready; all warps done reading VT
    }

    // epilogue -> g_ctx as pc'd tf32
    l0 += __shfl_xor_sync(0xffffffffu, l0, 1);
    l0 += __shfl_xor_sync(0xffffffffu, l0, 2);
    l1 += __shfl_xor_sync(0xffffffffu, l1, 1);
    l1 += __shfl_xor_sync(0xffffffffu, l1, 2);
    const float i0 = 1.f / l0, i1 = 1.f / l1;

    const int b = bh >> 3, h = bh & 7;
    #pragma unroll
    for (int nt = 0; nt < 8; nt++) {
        int c0 = nt * 8 + (t4 << 1);
        int col0 = h * 64 + (c0 & ~7) + PC(c0 & 7);
        int col1 = h * 64 + ((c0 + 1) & ~7) + PC((c0 + 1) & 7);
        g_ctx[((size_t)(b * Lq) + r0) * Dq + col0] = f2tf(acc[nt][0] * i0);
        g_ctx[((size_t)(b * Lq) + r0) * Dq + col1] = f2tf(acc[nt][1] * i0);
        g_ctx[((size_t)(b * Lq) + r1) * Dq + col0] = f2tf(acc[nt][2] * i1);
        g_ctx[((size_t)(b * Lq) + r1) * Dq + col1] = f2tf(acc[nt][3] * i1);
    }
}

// ---------------- launch --------------------------------------------------------
#define GEMM_SMEM (6 * GST * 4)      // 110592 bytes

extern "C" void kernel_launch(void* const* d_in, const int* in_sizes, int n_in,
                              void* d_out, int out_size)
{
    const float* q  = (const float*)d_in[0];
    const float* k  = (const float*)d_in[1];
    const float* v  = (const float*)d_in[2];
    // d_in[3] = mask (int32 tril) — causality handled analytically
    const float* Wq = (const float*)d_in[4];
    const float* bq = (const float*)d_in[5];
    const float* Wk = (const float*)d_in[6];
    const float* bk = (const float*)d_in[7];
    const float* Wv = (const float*)d_in[8];
    const float* bv = (const float*)d_in[9];
    const float* Wo = (const float*)d_in[10];
    const float* bo = (const float*)d_in[11];
    float* out = (float*)d_out;

    cudaFuncSetAttribute(gemm_fast, cudaFuncAttributeMaxDynamicSharedMemorySize,
                         GEMM_SMEM);

    prep_x<<<dim3(Mrows * 128 / 256, 3), 256>>>(q, k, v);
    prep_w<<<dim3(16, 16, 4), dim3(32, 32)>>>(Wq, Wk, Wv, Wo);

    gemm_fast<<<dim3(4, 64, 3), 256, GEMM_SMEM>>>(bq, bk, bv, nullptr, 0);

    attn_tf32<<<dim3(64, BHq), 128>>>();

    gemm_fast<<<dim3(4, 64, 1), 256, GEMM_SMEM>>>(bo, nullptr, nullptr, out, 3);
}